// round 6
// baseline (speedup 1.0000x reference)
#include <cuda_runtime.h>
#include <cuda_bf16.h>
#include <mma.h>

using namespace nvcuda;

// Problem constants
#define TT 128
#define BB 64
#define HH 2048
#define LL 4
#define CC 10
#define KIN 144           // IN*ND = 48*3
#define NTB (TT*BB)       // 8192 rows
#define BH  (BB*HH)       // 131072

// GEMM tiling
#define BM 128
#define BN 128
#define BK 32
#define LDS 40            // padded smem leading dim (multiple of 8)

// ---------------- scratch (device globals; no allocation) ----------------
__device__ float g_z[NTB * HH];      // GEMM output / scan input   (64 MB)
__device__ float g_h[NTB * HH];      // scan output / next input   (64 MB)
__device__ float g_psum[BB * HH];    // per-(b,h) partial sums for BN
__device__ float g_psq [BB * HH];    // per-(b,h) partial sum-of-squares
__device__ float g_scale[HH];
__device__ float g_shift[HH];

__device__ __forceinline__ float to_tf32(float x) {
    float r;
    asm("cvt.rna.tf32.f32 %0, %1;" : "=f"(r) : "f"(x));
    return r;
}

// ---------------------------------------------------------------------------
// GEMM: C[m,n] = sum_k Anorm[m,k] * W[n,k]
//   A row-major [M=8192, K], W row-major [N=2048, K] (so B is K-major = col_major)
//   Anorm[m,k] = scale ? A[m,k]*scale[k]+shift[k] : A[m,k]   (BN folded in)
//   bias is NOT added here (folded into the scan).
// TF32 wmma m16n16k8, block tile 128x128x32, 8 warps each 64x32.
// ---------------------------------------------------------------------------
__global__ __launch_bounds__(256) void gemm_tf32_kernel(
    const float* __restrict__ A,
    const float* __restrict__ W,
    float*       __restrict__ Cmat,
    const float* __restrict__ scale,
    const float* __restrict__ shift,
    int K)
{
    __shared__ __align__(128) float As[BM * LDS];
    __shared__ __align__(128) float Bs[BN * LDS];

    const int bm  = blockIdx.y * BM;
    const int bn  = blockIdx.x * BN;
    const int tid = threadIdx.x;
    const int warp = tid >> 5;
    const int wm = warp >> 2;   // 0..1  -> 64-row stripe
    const int wn = warp & 3;    // 0..3  -> 32-col stripe

    wmma::fragment<wmma::accumulator, 16, 16, 8, float> acc[4][2];
#pragma unroll
    for (int i = 0; i < 4; i++)
#pragma unroll
        for (int j = 0; j < 2; j++)
            wmma::fill_fragment(acc[i][j], 0.0f);

    for (int k0 = 0; k0 < K; k0 += BK) {
        const bool full = (k0 + BK <= K);

        // ---- load A tile: 128 rows x 32 cols (each thread: 4 x float4) ----
#pragma unroll
        for (int r = 0; r < 4; r++) {
            int lin = tid + r * 256;
            int row = lin >> 3;            // 0..127
            int c4  = (lin & 7) * 4;       // 0,4,...,28
            int gk  = k0 + c4;
            float4 v;
            if (full) {
                v = *(const float4*)(A + (size_t)(bm + row) * K + gk);
            } else {
                float t0 = (gk + 0 < K) ? A[(size_t)(bm + row) * K + gk + 0] : 0.f;
                float t1 = (gk + 1 < K) ? A[(size_t)(bm + row) * K + gk + 1] : 0.f;
                float t2 = (gk + 2 < K) ? A[(size_t)(bm + row) * K + gk + 2] : 0.f;
                float t3 = (gk + 3 < K) ? A[(size_t)(bm + row) * K + gk + 3] : 0.f;
                v = make_float4(t0, t1, t2, t3);
            }
            if (scale) {   // BN of previous layer folded into the A read
                v.x = fmaf(v.x, scale[gk + 0], shift[gk + 0]);
                v.y = fmaf(v.y, scale[gk + 1], shift[gk + 1]);
                v.z = fmaf(v.z, scale[gk + 2], shift[gk + 2]);
                v.w = fmaf(v.w, scale[gk + 3], shift[gk + 3]);
            }
            v.x = to_tf32(v.x); v.y = to_tf32(v.y);
            v.z = to_tf32(v.z); v.w = to_tf32(v.w);
            *(float4*)(As + row * LDS + c4) = v;
        }

        // ---- load W tile: 128 rows (n) x 32 cols (k) ----
#pragma unroll
        for (int r = 0; r < 4; r++) {
            int lin = tid + r * 256;
            int row = lin >> 3;
            int c4  = (lin & 7) * 4;
            int gk  = k0 + c4;
            float4 v;
            if (full) {
                v = *(const float4*)(W + (size_t)(bn + row) * K + gk);
            } else {
                float t0 = (gk + 0 < K) ? W[(size_t)(bn + row) * K + gk + 0] : 0.f;
                float t1 = (gk + 1 < K) ? W[(size_t)(bn + row) * K + gk + 1] : 0.f;
                float t2 = (gk + 2 < K) ? W[(size_t)(bn + row) * K + gk + 2] : 0.f;
                float t3 = (gk + 3 < K) ? W[(size_t)(bn + row) * K + gk + 3] : 0.f;
                v = make_float4(t0, t1, t2, t3);
            }
            v.x = to_tf32(v.x); v.y = to_tf32(v.y);
            v.z = to_tf32(v.z); v.w = to_tf32(v.w);
            *(float4*)(Bs + row * LDS + c4) = v;
        }

        __syncthreads();

        // ---- compute: 4 k-steps of m16n16k8 ----
#pragma unroll
        for (int kk = 0; kk < BK; kk += 8) {
            wmma::fragment<wmma::matrix_a, 16, 16, 8, wmma::precision::tf32, wmma::row_major> af[4];
            wmma::fragment<wmma::matrix_b, 16, 16, 8, wmma::precision::tf32, wmma::col_major> bf[2];
#pragma unroll
            for (int i = 0; i < 4; i++)
                wmma::load_matrix_sync(af[i], As + (wm * 64 + i * 16) * LDS + kk, LDS);
#pragma unroll
            for (int j = 0; j < 2; j++)
                wmma::load_matrix_sync(bf[j], Bs + (wn * 32 + j * 16) * LDS + kk, LDS);
#pragma unroll
            for (int i = 0; i < 4; i++)
#pragma unroll
                for (int j = 0; j < 2; j++)
                    wmma::mma_sync(acc[i][j], af[i], bf[j], acc[i][j]);
        }
        __syncthreads();
    }

#pragma unroll
    for (int i = 0; i < 4; i++)
#pragma unroll
        for (int j = 0; j < 2; j++)
            wmma::store_matrix_sync(
                Cmat + (size_t)(bm + wm * 64 + i * 16) * HH + (bn + wn * 32 + j * 16),
                acc[i][j], HH, wmma::mem_row_major);
}

// ---------------------------------------------------------------------------
// IndRNN scan: h_t = relu(z_t + bias + u * h_{t-1}), h_0 = 0.
// One thread per (b,h). Also writes deterministic per-(b,h) partial
// sums / sumsq for BatchNorm (no atomics -> bitwise deterministic).
// ---------------------------------------------------------------------------
__global__ __launch_bounds__(256) void scan_kernel(
    const float* __restrict__ z,
    float*       __restrict__ hout,
    const float* __restrict__ u,
    const float* __restrict__ bias)
{
    int idx = blockIdx.x * blockDim.x + threadIdx.x;  // b*HH + h
    if (idx >= BH) return;
    int ch = idx & (HH - 1);
    float uu = u[ch];
    float bb = bias[ch];

    float hprev = 0.f, s = 0.f, sq = 0.f;
#pragma unroll 8
    for (int t = 0; t < TT; t++) {
        float v = z[(size_t)t * BH + idx] + bb + uu * hprev;
        v = fmaxf(v, 0.f);
        hout[(size_t)t * BH + idx] = v;
        hprev = v;
        s  += v;
        sq += v * v;
    }
    g_psum[idx] = s;
    g_psq[idx]  = sq;
}

// ---------------------------------------------------------------------------
// BN params: reduce partials over B, compute scale/shift per channel.
//   scale = gamma * rsqrt(var + eps);  shift = beta - mean*scale
// ---------------------------------------------------------------------------
__global__ __launch_bounds__(256) void bn_params_kernel(
    const float* __restrict__ gamma,
    const float* __restrict__ beta)
{
    int h = blockIdx.x * blockDim.x + threadIdx.x;
    if (h >= HH) return;
    float s = 0.f, q = 0.f;
#pragma unroll 4
    for (int b = 0; b < BB; b++) {
        s += g_psum[b * HH + h];
        q += g_psq [b * HH + h];
    }
    const float inv_n = 1.0f / (float)(TT * BB);
    float mean = s * inv_n;
    float var  = q * inv_n - mean * mean;
    float sc   = gamma[h] * rsqrtf(var + 1e-5f);
    g_scale[h] = sc;
    g_shift[h] = beta[h] - mean * sc;
}

// ---------------------------------------------------------------------------
// Final projection: out[b,c] = sum_h (h_last[b,h]*scale+shift) * Wlast[c,h] + blast[c]
// One block per batch element; block-wide reduction of 10 accumulators.
// ---------------------------------------------------------------------------
__global__ __launch_bounds__(256) void final_kernel(
    const float* __restrict__ hlast,   // [B, H]
    const float* __restrict__ Wlast,   // [C, H]
    const float* __restrict__ blast,   // [C]
    float*       __restrict__ out)     // [B, C]
{
    int b   = blockIdx.x;
    int tid = threadIdx.x;

    float acc[CC];
#pragma unroll
    for (int c = 0; c < CC; c++) acc[c] = 0.f;

    for (int h = tid; h < HH; h += 256) {
        float v = fmaf(hlast[(size_t)b * HH + h], g_scale[h], g_shift[h]);
#pragma unroll
        for (int c = 0; c < CC; c++)
            acc[c] += v * Wlast[c * HH + h];
    }

    __shared__ float sred[CC * 256];
#pragma unroll
    for (int c = 0; c < CC; c++) sred[c * 256 + tid] = acc[c];
    __syncthreads();

    for (int st = 128; st > 0; st >>= 1) {
        if (tid < st) {
#pragma unroll
            for (int c = 0; c < CC; c++)
                sred[c * 256 + tid] += sred[c * 256 + tid + st];
        }
        __syncthreads();
    }
    if (tid < CC)
        out[b * CC + tid] = sred[tid * 256] + blast[tid];
}

// ---------------------------------------------------------------------------
extern "C" void kernel_launch(void* const* d_in, const int* in_sizes, int n_in,
                              void* d_out, int out_size)
{
    const float* x      = (const float*)d_in[0];  // [T,B,IN,ND] == [8192, 144]
    const float* W0     = (const float*)d_in[1];  // [H, 144]
    const float* Ws     = (const float*)d_in[2];  // [L-1, H, H]
    const float* bs     = (const float*)d_in[3];  // [L, H]
    const float* us     = (const float*)d_in[4];  // [L, H]
    const float* gammas = (const float*)d_in[5];  // [L, H]
    const float* betas  = (const float*)d_in[6];  // [L, H]
    const float* Wlast  = (const float*)d_in[7];  // [C, H]
    const float* blast  = (const float*)d_in[8];  // [C]
    float* out = (float*)d_out;

    float *z, *h;
    cudaGetSymbolAddress((void**)&z, g_z);
    cudaGetSymbolAddress((void**)&h, g_h);
    float *scale_p, *shift_p;
    cudaGetSymbolAddress((void**)&scale_p, g_scale);
    cudaGetSymbolAddress((void**)&shift_p, g_shift);

    dim3 gemm_grid(HH / BN, NTB / BM);   // (16, 64)

    for (int l = 0; l < LL; l++) {
        const float* A = (l == 0) ? x : h;
        const float* W = (l == 0) ? W0 : (Ws + (size_t)(l - 1) * HH * HH);
        int K = (l == 0) ? KIN : HH;
        const float* sc = (l == 0) ? nullptr : scale_p;
        const float* sh = (l == 0) ? nullptr : shift_p;

        gemm_tf32_kernel<<<gemm_grid, 256>>>(A, W, z, sc, sh, K);
        scan_kernel<<<BH / 256, 256>>>(z, h, us + (size_t)l * HH, bs + (size_t)l * HH);
        bn_params_kernel<<<HH / 256, 256>>>(gammas + (size_t)l * HH, betas + (size_t)l * HH);
    }

    final_kernel<<<BB, 256>>>(h + (size_t)(TT - 1) * BH, Wlast, blast, out);
}

// round 8
// speedup vs baseline: 1.2834x; 1.2834x over previous
#include <cuda_runtime.h>
#include <cuda_bf16.h>
#include <mma.h>
#include <cstdint>

using namespace nvcuda;

// Problem constants
#define TT 128
#define BB 64
#define HH 2048
#define LL 4
#define CC 10
#define KIN 144           // IN*ND = 48*3
#define NTB (TT*BB)       // 8192 rows
#define BH  (BB*HH)       // 131072

// GEMM tiling
#define BM 128
#define BN 128
#define BK 32
#define LDS 40            // padded smem leading dim (floats); rows 160B, 16B aligned
#define STAGES 3
#define STAGE_F ((BM + BN) * LDS)               // floats per stage (A then B)
#define GEMM_SMEM_BYTES (STAGES * STAGE_F * 4)  // 122880 B

// ---------------- scratch (device globals; no allocation) ----------------
__device__ __align__(128) float g_z[NTB * HH];      // GEMM output / scan input
__device__ __align__(128) float g_h[NTB * HH];      // scan output / next GEMM input
__device__ __align__(128) float g_x144[NTB * KIN];  // tf32-rounded x
__device__ __align__(128) float g_W0r[HH * KIN];    // tf32-rounded W0
__device__ __align__(128) float g_Wr[(LL - 1) * HH * HH]; // tf32-rounded Ws
__device__ float g_psum[BB * HH];
__device__ float g_psq [BB * HH];
__device__ float g_scale[HH];
__device__ float g_shift[HH];

__device__ __forceinline__ float to_tf32(float x) {
    float r;
    asm("cvt.rna.tf32.f32 %0, %1;" : "=f"(r) : "f"(x));
    return r;
}

__device__ __forceinline__ unsigned smem_u32(const void* p) {
    return (unsigned)__cvta_generic_to_shared(p);
}

__device__ __forceinline__ void cp_async16(unsigned dst, const void* src, int src_bytes) {
    asm volatile("cp.async.cg.shared.global [%0], [%1], 16, %2;\n"
                 :: "r"(dst), "l"(src), "r"(src_bytes));
}

// ---------------------------------------------------------------------------
// Elementwise tf32 rounding (float4 vectorized).
// ---------------------------------------------------------------------------
__global__ __launch_bounds__(256) void round_tf32_kernel(
    const float* __restrict__ in, float* __restrict__ out, int n4)
{
    int i = blockIdx.x * blockDim.x + threadIdx.x;
    if (i >= n4) return;
    float4 v = ((const float4*)in)[i];
    v.x = to_tf32(v.x); v.y = to_tf32(v.y);
    v.z = to_tf32(v.z); v.w = to_tf32(v.w);
    ((float4*)out)[i] = v;
}

// ---------------------------------------------------------------------------
// BN normalize in place: h = h*scale[ch] + shift[ch], optional tf32 round.
// ---------------------------------------------------------------------------
__global__ __launch_bounds__(256) void normalize_kernel(float* __restrict__ h, int rnd)
{
    int i = blockIdx.x * blockDim.x + threadIdx.x;   // float4 index
    if (i >= NTB * HH / 4) return;
    int ch = (i * 4) & (HH - 1);
    float4 v = ((float4*)h)[i];
    v.x = fmaf(v.x, g_scale[ch + 0], g_shift[ch + 0]);
    v.y = fmaf(v.y, g_scale[ch + 1], g_shift[ch + 1]);
    v.z = fmaf(v.z, g_scale[ch + 2], g_shift[ch + 2]);
    v.w = fmaf(v.w, g_scale[ch + 3], g_shift[ch + 3]);
    if (rnd) {
        v.x = to_tf32(v.x); v.y = to_tf32(v.y);
        v.z = to_tf32(v.z); v.w = to_tf32(v.w);
    }
    ((float4*)h)[i] = v;
}

// ---------------------------------------------------------------------------
// TF32 GEMM, 3-stage cp.async pipeline.
//   C[m,n] = sum_k A[m,k] * W[n,k]
//   A row-major [M, K] (pre-rounded tf32), W row-major [N, K] (pre-rounded).
// Block tile 128x128x32, 8 warps each 64x32, wmma m16n16k8.
// ---------------------------------------------------------------------------
__global__ __launch_bounds__(256) void gemm_tf32_pipe(
    const float* __restrict__ A,
    const float* __restrict__ W,
    float*       __restrict__ Cmat,
    int K)
{
    extern __shared__ float sm[];

    const int bm   = blockIdx.y * BM;
    const int bn   = blockIdx.x * BN;
    const int tid  = threadIdx.x;
    const int warp = tid >> 5;
    const int wm   = warp >> 2;   // 0..1
    const int wn   = warp & 3;    // 0..3

    wmma::fragment<wmma::accumulator, 16, 16, 8, float> acc[4][2];
#pragma unroll
    for (int i = 0; i < 4; i++)
#pragma unroll
        for (int j = 0; j < 2; j++)
            wmma::fill_fragment(acc[i][j], 0.0f);

    const int kIters = (K + BK - 1) / BK;

    // per-thread loader coordinates: 4 chunks per tile, 16B each
    const int lrow0 = tid >> 3;          // rows covered: lrow0 + 32*r
    const int lc4   = (tid & 7) * 4;     // k offset within tile

    auto load_stage = [&](int s, int k0) {
        float* As = sm + s * STAGE_F;
        float* Bs = As + BM * LDS;
#pragma unroll
        for (int r = 0; r < 4; r++) {
            int row = lrow0 + r * 32;
            int gk  = k0 + lc4;
            int sz  = (gk < K) ? 16 : 0;          // zero-fill beyond K
            int gks = (gk < K) ? gk : (K - 4);    // keep address in-bounds
            cp_async16(smem_u32(As + row * LDS + lc4),
                       A + (size_t)(bm + row) * K + gks, sz);
            cp_async16(smem_u32(Bs + row * LDS + lc4),
                       W + (size_t)(bn + row) * K + gks, sz);
        }
    };

    // prologue: stages 0 and 1
    load_stage(0, 0);
    asm volatile("cp.async.commit_group;");
    load_stage(1, BK);
    asm volatile("cp.async.commit_group;");

    for (int it = 0; it < kIters; it++) {
        asm volatile("cp.async.wait_group 1;");
        __syncthreads();

        // issue load for it+2 (that stage's data was consumed in iter it-1;
        // all threads passed the sync above, so overwrite is safe)
        int nk = it + STAGES - 1;
        if (nk < kIters) load_stage(nk % STAGES, nk * BK);
        asm volatile("cp.async.commit_group;");   // empty groups keep count uniform

        // compute current stage
        const float* As = sm + (it % STAGES) * STAGE_F;
        const float* Bs = As + BM * LDS;
#pragma unroll
        for (int kk = 0; kk < BK; kk += 8) {
            wmma::fragment<wmma::matrix_a, 16, 16, 8, wmma::precision::tf32, wmma::row_major> af[4];
            wmma::fragment<wmma::matrix_b, 16, 16, 8, wmma::precision::tf32, wmma::col_major> bf[2];
#pragma unroll
            for (int i = 0; i < 4; i++)
                wmma::load_matrix_sync(af[i], As + (wm * 64 + i * 16) * LDS + kk, LDS);
#pragma unroll
            for (int j = 0; j < 2; j++)
                wmma::load_matrix_sync(bf[j], Bs + (wn * 32 + j * 16) * LDS + kk, LDS);
#pragma unroll
            for (int i = 0; i < 4; i++)
#pragma unroll
                for (int j = 0; j < 2; j++)
                    wmma::mma_sync(acc[i][j], af[i], bf[j], acc[i][j]);
        }
    }

#pragma unroll
    for (int i = 0; i < 4; i++)
#pragma unroll
        for (int j = 0; j < 2; j++)
            wmma::store_matrix_sync(
                Cmat + (size_t)(bm + wm * 64 + i * 16) * HH + (bn + wn * 32 + j * 16),
                acc[i][j], HH, wmma::mem_row_major);
}

// ---------------------------------------------------------------------------
// IndRNN scan: h_t = relu(z_t + bias + u * h_{t-1}); deterministic BN partials.
// ---------------------------------------------------------------------------
__global__ __launch_bounds__(256) void scan_kernel(
    const float* __restrict__ z,
    float*       __restrict__ hout,
    const float* __restrict__ u,
    const float* __restrict__ bias)
{
    int idx = blockIdx.x * blockDim.x + threadIdx.x;  // b*HH + h
    if (idx >= BH) return;
    int ch = idx & (HH - 1);
    float uu = u[ch];
    float bb = bias[ch];

    float hprev = 0.f, s = 0.f, sq = 0.f;
#pragma unroll 8
    for (int t = 0; t < TT; t++) {
        float v = z[(size_t)t * BH + idx] + bb + uu * hprev;
        v = fmaxf(v, 0.f);
        hout[(size_t)t * BH + idx] = v;
        hprev = v;
        s  += v;
        sq += v * v;
    }
    g_psum[idx] = s;
    g_psq[idx]  = sq;
}

// ---------------------------------------------------------------------------
// BN params: scale = gamma * rsqrt(var+eps); shift = beta - mean*scale
// ---------------------------------------------------------------------------
__global__ __launch_bounds__(256) void bn_params_kernel(
    const float* __restrict__ gamma,
    const float* __restrict__ beta)
{
    int h = blockIdx.x * blockDim.x + threadIdx.x;
    if (h >= HH) return;
    float s = 0.f, q = 0.f;
#pragma unroll 4
    for (int b = 0; b < BB; b++) {
        s += g_psum[b * HH + h];
        q += g_psq [b * HH + h];
    }
    const float inv_n = 1.0f / (float)(TT * BB);
    float mean = s * inv_n;
    float var  = q * inv_n - mean * mean;
    float sc   = gamma[h] * rsqrtf(var + 1e-5f);
    g_scale[h] = sc;
    g_shift[h] = beta[h] - mean * sc;
}

// ---------------------------------------------------------------------------
// Final projection: out[b,c] = sum_h hnorm[b,h] * Wlast[c,h] + blast[c]
// ---------------------------------------------------------------------------
__global__ __launch_bounds__(256) void final_kernel(
    const float* __restrict__ hlast,   // [B, H] normalized
    const float* __restrict__ Wlast,   // [C, H]
    const float* __restrict__ blast,   // [C]
    float*       __restrict__ out)     // [B, C]
{
    int b   = blockIdx.x;
    int tid = threadIdx.x;

    float acc[CC];
#pragma unroll
    for (int c = 0; c < CC; c++) acc[c] = 0.f;

    for (int h = tid; h < HH; h += 256) {
        float v = hlast[(size_t)b * HH + h];
#pragma unroll
        for (int c = 0; c < CC; c++)
            acc[c] += v * Wlast[c * HH + h];
    }

    __shared__ float sred[CC * 256];
#pragma unroll
    for (int c = 0; c < CC; c++) sred[c * 256 + tid] = acc[c];
    __syncthreads();

    for (int st = 128; st > 0; st >>= 1) {
        if (tid < st) {
#pragma unroll
            for (int c = 0; c < CC; c++)
                sred[c * 256 + tid] += sred[c * 256 + tid + st];
        }
        __syncthreads();
    }
    if (tid < CC)
        out[b * CC + tid] = sred[tid * 256] + blast[tid];
}

// ---------------------------------------------------------------------------
extern "C" void kernel_launch(void* const* d_in, const int* in_sizes, int n_in,
                              void* d_out, int out_size)
{
    const float* x      = (const float*)d_in[0];  // [8192, 144]
    const float* W0     = (const float*)d_in[1];  // [H, 144]
    const float* Ws     = (const float*)d_in[2];  // [L-1, H, H]
    const float* bs     = (const float*)d_in[3];
    const float* us     = (const float*)d_in[4];
    const float* gammas = (const float*)d_in[5];
    const float* betas  = (const float*)d_in[6];
    const float* Wlast  = (const float*)d_in[7];
    const float* blast  = (const float*)d_in[8];
    float* out = (float*)d_out;

    float *z, *h, *xr, *w0r, *wr;
    cudaGetSymbolAddress((void**)&z,   g_z);
    cudaGetSymbolAddress((void**)&h,   g_h);
    cudaGetSymbolAddress((void**)&xr,  g_x144);
    cudaGetSymbolAddress((void**)&w0r, g_W0r);
    cudaGetSymbolAddress((void**)&wr,  g_Wr);

    // not stream-ordered; safe under graph capture, idempotent
    cudaFuncSetAttribute(gemm_tf32_pipe,
                         cudaFuncAttributeMaxDynamicSharedMemorySize,
                         GEMM_SMEM_BYTES);

    // pre-round all GEMM operands to tf32 (keeps numerics == wmma rna path)
    {
        int n4;
        n4 = NTB * KIN / 4;
        round_tf32_kernel<<<(n4 + 255) / 256, 256>>>(x, xr, n4);
        n4 = HH * KIN / 4;
        round_tf32_kernel<<<(n4 + 255) / 256, 256>>>(W0, w0r, n4);
        n4 = (LL - 1) * HH * HH / 4;
        round_tf32_kernel<<<(n4 + 255) / 256, 256>>>(Ws, wr, n4);
    }

    dim3 gemm_grid(HH / BN, NTB / BM);   // (16, 64)
    const int norm_blocks = (NTB * HH / 4 + 255) / 256;

    for (int l = 0; l < LL; l++) {
        const float* A = (l == 0) ? xr : h;
        const float* W = (l == 0) ? w0r : (wr + (size_t)(l - 1) * HH * HH);
        int K = (l == 0) ? KIN : HH;

        gemm_tf32_pipe<<<gemm_grid, 256, GEMM_SMEM_BYTES>>>(A, W, z, K);
        scan_kernel<<<BH / 256, 256>>>(z, h, us + (size_t)l * HH, bs + (size_t)l * HH);
        bn_params_kernel<<<HH / 256, 256>>>(gammas + (size_t)l * HH, betas + (size_t)l * HH);
        // layers 0..2: normalize + tf32-round (feeds next GEMM);
        // layer 3: normalize only (feeds fp32 final projection)
        normalize_kernel<<<norm_blocks, 256>>>(h, (l < LL - 1) ? 1 : 0);
    }

    final_kernel<<<BB, 256>>>(h + (size_t)(TT - 1) * BH, Wlast, blast, out);
}

// round 10
// speedup vs baseline: 1.4009x; 1.0915x over previous
#include <cuda_runtime.h>
#include <cuda_bf16.h>
#include <mma.h>
#include <cstdint>

using namespace nvcuda;

// Problem constants
#define TT 128
#define BB 64
#define HH 2048
#define LL 4
#define CC 10
#define KIN 144           // IN*ND = 48*3
#define NTB (TT*BB)       // 8192 rows
#define BH  (BB*HH)       // 131072

// GEMM tiling
#define BM 128
#define BN 128
#define BK 32
#define LDS 36            // padded smem pitch (floats): 144B rows, 16B aligned
#define STAGES 3
#define STAGE_F ((BM + BN) * LDS)               // floats per stage (A then B)
#define GEMM_SMEM_BYTES (STAGES * STAGE_F * 4)  // 110592 B -> 2 CTAs/SM

// ---------------- scratch (device globals; no allocation) ----------------
__device__ __align__(128) float g_z[NTB * HH];      // GEMM output / scan input
__device__ __align__(128) float g_h[NTB * HH];      // scan output / next GEMM input
__device__ __align__(128) float g_x144[NTB * KIN];  // tf32-rounded x
__device__ __align__(128) float g_W0r[HH * KIN];    // tf32-rounded W0
__device__ __align__(128) float g_Wr[(LL - 1) * HH * HH]; // tf32-rounded Ws
__device__ float g_psum[BB * HH];
__device__ float g_psq [BB * HH];
__device__ float g_scale[HH];
__device__ float g_shift[HH];

__device__ __forceinline__ float to_tf32(float x) {
    float r;
    asm("cvt.rna.tf32.f32 %0, %1;" : "=f"(r) : "f"(x));
    return r;
}

__device__ __forceinline__ unsigned smem_u32(const void* p) {
    return (unsigned)__cvta_generic_to_shared(p);
}

__device__ __forceinline__ void cp_async16(unsigned dst, const void* src, int src_bytes) {
    asm volatile("cp.async.cg.shared.global [%0], [%1], 16, %2;\n"
                 :: "r"(dst), "l"(src), "r"(src_bytes));
}

// ---------------------------------------------------------------------------
// Elementwise tf32 rounding (float4 vectorized).
// ---------------------------------------------------------------------------
__global__ __launch_bounds__(256) void round_tf32_kernel(
    const float* __restrict__ in, float* __restrict__ out, int n4)
{
    int i = blockIdx.x * blockDim.x + threadIdx.x;
    if (i >= n4) return;
    float4 v = ((const float4*)in)[i];
    v.x = to_tf32(v.x); v.y = to_tf32(v.y);
    v.z = to_tf32(v.z); v.w = to_tf32(v.w);
    ((float4*)out)[i] = v;
}

// ---------------------------------------------------------------------------
// BN normalize in place: h = h*scale[ch] + shift[ch], optional tf32 round.
// ---------------------------------------------------------------------------
__global__ __launch_bounds__(256) void normalize_kernel(float* __restrict__ h, int rnd)
{
    int i = blockIdx.x * blockDim.x + threadIdx.x;   // float4 index
    if (i >= NTB * HH / 4) return;
    int ch = (i * 4) & (HH - 1);
    float4 v = ((float4*)h)[i];
    v.x = fmaf(v.x, g_scale[ch + 0], g_shift[ch + 0]);
    v.y = fmaf(v.y, g_scale[ch + 1], g_shift[ch + 1]);
    v.z = fmaf(v.z, g_scale[ch + 2], g_shift[ch + 2]);
    v.w = fmaf(v.w, g_scale[ch + 3], g_shift[ch + 3]);
    if (rnd) {
        v.x = to_tf32(v.x); v.y = to_tf32(v.y);
        v.z = to_tf32(v.z); v.w = to_tf32(v.w);
    }
    ((float4*)h)[i] = v;
}

// ---------------------------------------------------------------------------
// TF32 GEMM, 3-stage cp.async pipeline, 2 CTAs/SM.
//   C[m,n] = sum_k A[m,k] * W[n,k]
//   A row-major [M, K] (pre-rounded tf32), W row-major [N, K] (pre-rounded).
// Block tile 128x128x32, 8 warps each 64x32, wmma m16n16k8.
// ---------------------------------------------------------------------------
__global__ __launch_bounds__(256, 2) void gemm_tf32_pipe(
    const float* __restrict__ A,
    const float* __restrict__ W,
    float*       __restrict__ Cmat,
    int K)
{
    extern __shared__ float sm[];

    const int bm   = blockIdx.y * BM;
    const int bn   = blockIdx.x * BN;
    const int tid  = threadIdx.x;
    const int warp = tid >> 5;
    const int wm   = warp >> 2;   // 0..1
    const int wn   = warp & 3;    // 0..3

    wmma::fragment<wmma::accumulator, 16, 16, 8, float> acc[4][2];
#pragma unroll
    for (int i = 0; i < 4; i++)
#pragma unroll
        for (int j = 0; j < 2; j++)
            wmma::fill_fragment(acc[i][j], 0.0f);

    const int kIters = (K + BK - 1) / BK;

    // per-thread loader coordinates: 4 chunks per tile, 16B each
    const int lrow0 = tid >> 3;          // rows covered: lrow0 + 32*r
    const int lc4   = (tid & 7) * 4;     // k offset within tile

    auto load_stage = [&](int s, int k0) {
        float* As = sm + s * STAGE_F;
        float* Bs = As + BM * LDS;
#pragma unroll
        for (int r = 0; r < 4; r++) {
            int row = lrow0 + r * 32;
            int gk  = k0 + lc4;
            int sz  = (gk < K) ? 16 : 0;          // zero-fill beyond K
            int gks = (gk < K) ? gk : (K - 4);    // keep address in-bounds
            cp_async16(smem_u32(As + row * LDS + lc4),
                       A + (size_t)(bm + row) * K + gks, sz);
            cp_async16(smem_u32(Bs + row * LDS + lc4),
                       W + (size_t)(bn + row) * K + gks, sz);
        }
    };

    // prologue: stages 0 and 1
    load_stage(0, 0);
    asm volatile("cp.async.commit_group;");
    load_stage(1, BK);
    asm volatile("cp.async.commit_group;");

    for (int it = 0; it < kIters; it++) {
        asm volatile("cp.async.wait_group 1;");
        __syncthreads();

        // issue load for it+2 (that stage's data was consumed in iter it-1;
        // all threads passed the sync above, so overwrite is safe)
        int nk = it + STAGES - 1;
        if (nk < kIters) load_stage(nk % STAGES, nk * BK);
        asm volatile("cp.async.commit_group;");   // empty groups keep count uniform

        // compute current stage
        const float* As = sm + (it % STAGES) * STAGE_F;
        const float* Bs = As + BM * LDS;
#pragma unroll
        for (int kk = 0; kk < BK; kk += 8) {
            wmma::fragment<wmma::matrix_a, 16, 16, 8, wmma::precision::tf32, wmma::row_major> af[4];
            wmma::fragment<wmma::matrix_b, 16, 16, 8, wmma::precision::tf32, wmma::col_major> bf[2];
#pragma unroll
            for (int i = 0; i < 4; i++)
                wmma::load_matrix_sync(af[i], As + (wm * 64 + i * 16) * LDS + kk, LDS);
#pragma unroll
            for (int j = 0; j < 2; j++)
                wmma::load_matrix_sync(bf[j], Bs + (wn * 32 + j * 16) * LDS + kk, LDS);
#pragma unroll
            for (int i = 0; i < 4; i++)
#pragma unroll
                for (int j = 0; j < 2; j++)
                    wmma::mma_sync(acc[i][j], af[i], bf[j], acc[i][j]);
        }
    }

#pragma unroll
    for (int i = 0; i < 4; i++)
#pragma unroll
        for (int j = 0; j < 2; j++)
            wmma::store_matrix_sync(
                Cmat + (size_t)(bm + wm * 64 + i * 16) * HH + (bn + wn * 32 + j * 16),
                acc[i][j], HH, wmma::mem_row_major);
}

// ---------------------------------------------------------------------------
// IndRNN scan: h_t = relu(z_t + bias + u * h_{t-1}); deterministic BN partials.
// ---------------------------------------------------------------------------
__global__ __launch_bounds__(256) void scan_kernel(
    const float* __restrict__ z,
    float*       __restrict__ hout,
    const float* __restrict__ u,
    const float* __restrict__ bias)
{
    int idx = blockIdx.x * blockDim.x + threadIdx.x;  // b*HH + h
    if (idx >= BH) return;
    int ch = idx & (HH - 1);
    float uu = u[ch];
    float bb = bias[ch];

    float hprev = 0.f, s = 0.f, sq = 0.f;
#pragma unroll 8
    for (int t = 0; t < TT; t++) {
        float v = z[(size_t)t * BH + idx] + bb + uu * hprev;
        v = fmaxf(v, 0.f);
        hout[(size_t)t * BH + idx] = v;
        hprev = v;
        s  += v;
        sq += v * v;
    }
    g_psum[idx] = s;
    g_psq[idx]  = sq;
}

// ---------------------------------------------------------------------------
// BN params: scale = gamma * rsqrt(var+eps); shift = beta - mean*scale
// ---------------------------------------------------------------------------
__global__ __launch_bounds__(256) void bn_params_kernel(
    const float* __restrict__ gamma,
    const float* __restrict__ beta)
{
    int h = blockIdx.x * blockDim.x + threadIdx.x;
    if (h >= HH) return;
    float s = 0.f, q = 0.f;
#pragma unroll 4
    for (int b = 0; b < BB; b++) {
        s += g_psum[b * HH + h];
        q += g_psq [b * HH + h];
    }
    const float inv_n = 1.0f / (float)(TT * BB);
    float mean = s * inv_n;
    float var  = q * inv_n - mean * mean;
    float sc   = gamma[h] * rsqrtf(var + 1e-5f);
    g_scale[h] = sc;
    g_shift[h] = beta[h] - mean * sc;
}

// ---------------------------------------------------------------------------
// Final projection: out[b,c] = sum_h hnorm[b,h] * Wlast[c,h] + blast[c]
// ---------------------------------------------------------------------------
__global__ __launch_bounds__(256) void final_kernel(
    const float* __restrict__ hlast,   // [B, H] normalized
    const float* __restrict__ Wlast,   // [C, H]
    const float* __restrict__ blast,   // [C]
    float*       __restrict__ out)     // [B, C]
{
    int b   = blockIdx.x;
    int tid = threadIdx.x;

    float acc[CC];
#pragma unroll
    for (int c = 0; c < CC; c++) acc[c] = 0.f;

    for (int h = tid; h < HH; h += 256) {
        float v = hlast[(size_t)b * HH + h];
#pragma unroll
        for (int c = 0; c < CC; c++)
            acc[c] += v * Wlast[c * HH + h];
    }

    __shared__ float sred[CC * 256];
#pragma unroll
    for (int c = 0; c < CC; c++) sred[c * 256 + tid] = acc[c];
    __syncthreads();

    for (int st = 128; st > 0; st >>= 1) {
        if (tid < st) {
#pragma unroll
            for (int c = 0; c < CC; c++)
                sred[c * 256 + tid] += sred[c * 256 + tid + st];
        }
        __syncthreads();
    }
    if (tid < CC)
        out[b * CC + tid] = sred[tid * 256] + blast[tid];
}

// ---------------------------------------------------------------------------
extern "C" void kernel_launch(void* const* d_in, const int* in_sizes, int n_in,
                              void* d_out, int out_size)
{
    const float* x      = (const float*)d_in[0];  // [8192, 144]
    const float* W0     = (const float*)d_in[1];  // [H, 144]
    const float* Ws     = (const float*)d_in[2];  // [L-1, H, H]
    const float* bs     = (const float*)d_in[3];
    const float* us     = (const float*)d_in[4];
    const float* gammas = (const float*)d_in[5];
    const float* betas  = (const float*)d_in[6];
    const float* Wlast  = (const float*)d_in[7];
    const float* blast  = (const float*)d_in[8];
    float* out = (float*)d_out;

    float *z, *h, *xr, *w0r, *wr;
    cudaGetSymbolAddress((void**)&z,   g_z);
    cudaGetSymbolAddress((void**)&h,   g_h);
    cudaGetSymbolAddress((void**)&xr,  g_x144);
    cudaGetSymbolAddress((void**)&w0r, g_W0r);
    cudaGetSymbolAddress((void**)&wr,  g_Wr);

    cudaFuncSetAttribute(gemm_tf32_pipe,
                         cudaFuncAttributeMaxDynamicSharedMemorySize,
                         GEMM_SMEM_BYTES);

    // pre-round all GEMM operands to tf32 (keeps numerics == wmma rna path)
    {
        int n4;
        n4 = NTB * KIN / 4;
        round_tf32_kernel<<<(n4 + 255) / 256, 256>>>(x, xr, n4);
        n4 = HH * KIN / 4;
        round_tf32_kernel<<<(n4 + 255) / 256, 256>>>(W0, w0r, n4);
        n4 = (LL - 1) * HH * HH / 4;
        round_tf32_kernel<<<(n4 + 255) / 256, 256>>>(Ws, wr, n4);
    }

    dim3 gemm_grid(HH / BN, NTB / BM);   // (16, 64)
    const int norm_blocks = (NTB * HH / 4 + 255) / 256;

    for (int l = 0; l < LL; l++) {
        const float* A = (l == 0) ? xr : h;
        const float* W = (l == 0) ? w0r : (wr + (size_t)(l - 1) * HH * HH);
        int K = (l == 0) ? KIN : HH;

        gemm_tf32_pipe<<<gemm_grid, 256, GEMM_SMEM_BYTES>>>(A, W, z, K);
        scan_kernel<<<BH / 256, 256>>>(z, h, us + (size_t)l * HH, bs + (size_t)l * HH);
        bn_params_kernel<<<HH / 256, 256>>>(gammas + (size_t)l * HH, betas + (size_t)l * HH);
        // layers 0..2: normalize + tf32-round (feeds next GEMM);
        // layer 3: normalize only (feeds fp32 final projection)
        normalize_kernel<<<norm_blocks, 256>>>(h, (l < LL - 1) ? 1 : 0);
    }

    final_kernel<<<BB, 256>>>(h + (size_t)(TT - 1) * BH, Wlast, blast, out);
}

// round 11
// speedup vs baseline: 1.4010x; 1.0001x over previous
#include <cuda_runtime.h>
#include <cuda_bf16.h>
#include <mma.h>
#include <cstdint>

using namespace nvcuda;

// Problem constants
#define TT 128
#define BB 64
#define HH 2048
#define LL 4
#define CC 10
#define KIN 144           // IN*ND = 48*3
#define NTB (TT*BB)       // 8192 rows
#define BH  (BB*HH)       // 131072

// GEMM tiling
#define BM 128
#define BN 128
#define BK 32
#define LDS 36            // padded smem pitch (floats): 144B rows, 16B aligned
#define STAGES 3
#define STAGE_F ((BM + BN) * LDS)               // floats per stage (A then B)
#define GEMM_SMEM_BYTES (STAGES * STAGE_F * 4)  // 110592 B -> 2 CTAs/SM

// ---------------- scratch (device globals; no allocation) ----------------
__device__ __align__(128) float g_z[NTB * HH];      // GEMM output / scan input
__device__ __align__(128) float g_h[NTB * HH];      // scan output / next GEMM input
__device__ __align__(128) float g_x144[NTB * KIN];  // tf32-rounded x
__device__ __align__(128) float g_W0r[HH * KIN];    // tf32-rounded W0
__device__ __align__(128) float g_Wr[(LL - 1) * HH * HH]; // tf32-rounded Ws
__device__ float g_psum[BB * HH];
__device__ float g_psq [BB * HH];
__device__ float g_scale[HH];
__device__ float g_shift[HH];

__device__ __forceinline__ float to_tf32(float x) {
    float r;
    asm("cvt.rna.tf32.f32 %0, %1;" : "=f"(r) : "f"(x));
    return r;
}

__device__ __forceinline__ unsigned smem_u32(const void* p) {
    return (unsigned)__cvta_generic_to_shared(p);
}

__device__ __forceinline__ void cp_async16(unsigned dst, const void* src, int src_bytes) {
    asm volatile("cp.async.cg.shared.global [%0], [%1], 16, %2;\n"
                 :: "r"(dst), "l"(src), "r"(src_bytes));
}

// ---------------------------------------------------------------------------
// Elementwise tf32 rounding (float4 vectorized).
// ---------------------------------------------------------------------------
__global__ __launch_bounds__(256) void round_tf32_kernel(
    const float* __restrict__ in, float* __restrict__ out, int n4)
{
    int i = blockIdx.x * blockDim.x + threadIdx.x;
    if (i >= n4) return;
    float4 v = ((const float4*)in)[i];
    v.x = to_tf32(v.x); v.y = to_tf32(v.y);
    v.z = to_tf32(v.z); v.w = to_tf32(v.w);
    ((float4*)out)[i] = v;
}

// ---------------------------------------------------------------------------
// BN normalize in place: h = h*scale[ch] + shift[ch], optional tf32 round.
// ---------------------------------------------------------------------------
__global__ __launch_bounds__(256) void normalize_kernel(float* __restrict__ h, int rnd)
{
    int i = blockIdx.x * blockDim.x + threadIdx.x;   // float4 index
    if (i >= NTB * HH / 4) return;
    int ch = (i * 4) & (HH - 1);
    float4 v = ((float4*)h)[i];
    v.x = fmaf(v.x, g_scale[ch + 0], g_shift[ch + 0]);
    v.y = fmaf(v.y, g_scale[ch + 1], g_shift[ch + 1]);
    v.z = fmaf(v.z, g_scale[ch + 2], g_shift[ch + 2]);
    v.w = fmaf(v.w, g_scale[ch + 3], g_shift[ch + 3]);
    if (rnd) {
        v.x = to_tf32(v.x); v.y = to_tf32(v.y);
        v.z = to_tf32(v.z); v.w = to_tf32(v.w);
    }
    ((float4*)h)[i] = v;
}

// ---------------------------------------------------------------------------
// TF32 GEMM, 3-stage cp.async pipeline, 2 CTAs/SM.
//   C[m,n] = sum_k A[m,k] * W[n,k]
//   A row-major [M, K] (pre-rounded tf32), W row-major [N, K] (pre-rounded).
// Block tile 128x128x32, 8 warps each 64x32, wmma m16n16k8.
// ---------------------------------------------------------------------------
__global__ __launch_bounds__(256, 2) void gemm_tf32_pipe(
    const float* __restrict__ A,
    const float* __restrict__ W,
    float*       __restrict__ Cmat,
    int K)
{
    extern __shared__ float sm[];

    const int bm   = blockIdx.y * BM;
    const int bn   = blockIdx.x * BN;
    const int tid  = threadIdx.x;
    const int warp = tid >> 5;
    const int wm   = warp >> 2;   // 0..1
    const int wn   = warp & 3;    // 0..3

    wmma::fragment<wmma::accumulator, 16, 16, 8, float> acc[4][2];
#pragma unroll
    for (int i = 0; i < 4; i++)
#pragma unroll
        for (int j = 0; j < 2; j++)
            wmma::fill_fragment(acc[i][j], 0.0f);

    const int kIters = (K + BK - 1) / BK;

    // per-thread loader coordinates: 4 chunks per tile, 16B each
    const int lrow0 = tid >> 3;          // rows covered: lrow0 + 32*r
    const int lc4   = (tid & 7) * 4;     // k offset within tile

    auto load_stage = [&](int s, int k0) {
        float* As = sm + s * STAGE_F;
        float* Bs = As + BM * LDS;
#pragma unroll
        for (int r = 0; r < 4; r++) {
            int row = lrow0 + r * 32;
            int gk  = k0 + lc4;
            int sz  = (gk < K) ? 16 : 0;          // zero-fill beyond K
            int gks = (gk < K) ? gk : (K - 4);    // keep address in-bounds
            cp_async16(smem_u32(As + row * LDS + lc4),
                       A + (size_t)(bm + row) * K + gks, sz);
            cp_async16(smem_u32(Bs + row * LDS + lc4),
                       W + (size_t)(bn + row) * K + gks, sz);
        }
    };

    // prologue: stages 0 and 1
    load_stage(0, 0);
    asm volatile("cp.async.commit_group;");
    load_stage(1, BK);
    asm volatile("cp.async.commit_group;");

    for (int it = 0; it < kIters; it++) {
        asm volatile("cp.async.wait_group 1;");
        __syncthreads();

        // issue load for it+2 (that stage's data was consumed in iter it-1;
        // all threads passed the sync above, so overwrite is safe)
        int nk = it + STAGES - 1;
        if (nk < kIters) load_stage(nk % STAGES, nk * BK);
        asm volatile("cp.async.commit_group;");   // empty groups keep count uniform

        // compute current stage
        const float* As = sm + (it % STAGES) * STAGE_F;
        const float* Bs = As + BM * LDS;
#pragma unroll
        for (int kk = 0; kk < BK; kk += 8) {
            wmma::fragment<wmma::matrix_a, 16, 16, 8, wmma::precision::tf32, wmma::row_major> af[4];
            wmma::fragment<wmma::matrix_b, 16, 16, 8, wmma::precision::tf32, wmma::col_major> bf[2];
#pragma unroll
            for (int i = 0; i < 4; i++)
                wmma::load_matrix_sync(af[i], As + (wm * 64 + i * 16) * LDS + kk, LDS);
#pragma unroll
            for (int j = 0; j < 2; j++)
                wmma::load_matrix_sync(bf[j], Bs + (wn * 32 + j * 16) * LDS + kk, LDS);
#pragma unroll
            for (int i = 0; i < 4; i++)
#pragma unroll
                for (int j = 0; j < 2; j++)
                    wmma::mma_sync(acc[i][j], af[i], bf[j], acc[i][j]);
        }
    }

#pragma unroll
    for (int i = 0; i < 4; i++)
#pragma unroll
        for (int j = 0; j < 2; j++)
            wmma::store_matrix_sync(
                Cmat + (size_t)(bm + wm * 64 + i * 16) * HH + (bn + wn * 32 + j * 16),
                acc[i][j], HH, wmma::mem_row_major);
}

// ---------------------------------------------------------------------------
// IndRNN scan: h_t = relu(z_t + bias + u * h_{t-1}); deterministic BN partials.
// ---------------------------------------------------------------------------
__global__ __launch_bounds__(256) void scan_kernel(
    const float* __restrict__ z,
    float*       __restrict__ hout,
    const float* __restrict__ u,
    const float* __restrict__ bias)
{
    int idx = blockIdx.x * blockDim.x + threadIdx.x;  // b*HH + h
    if (idx >= BH) return;
    int ch = idx & (HH - 1);
    float uu = u[ch];
    float bb = bias[ch];

    float hprev = 0.f, s = 0.f, sq = 0.f;
#pragma unroll 8
    for (int t = 0; t < TT; t++) {
        float v = z[(size_t)t * BH + idx] + bb + uu * hprev;
        v = fmaxf(v, 0.f);
        hout[(size_t)t * BH + idx] = v;
        hprev = v;
        s  += v;
        sq += v * v;
    }
    g_psum[idx] = s;
    g_psq[idx]  = sq;
}

// ---------------------------------------------------------------------------
// BN params: scale = gamma * rsqrt(var+eps); shift = beta - mean*scale
// ---------------------------------------------------------------------------
__global__ __launch_bounds__(256) void bn_params_kernel(
    const float* __restrict__ gamma,
    const float* __restrict__ beta)
{
    int h = blockIdx.x * blockDim.x + threadIdx.x;
    if (h >= HH) return;
    float s = 0.f, q = 0.f;
#pragma unroll 4
    for (int b = 0; b < BB; b++) {
        s += g_psum[b * HH + h];
        q += g_psq [b * HH + h];
    }
    const float inv_n = 1.0f / (float)(TT * BB);
    float mean = s * inv_n;
    float var  = q * inv_n - mean * mean;
    float sc   = gamma[h] * rsqrtf(var + 1e-5f);
    g_scale[h] = sc;
    g_shift[h] = beta[h] - mean * sc;
}

// ---------------------------------------------------------------------------
// Final projection: out[b,c] = sum_h hnorm[b,h] * Wlast[c,h] + blast[c]
// ---------------------------------------------------------------------------
__global__ __launch_bounds__(256) void final_kernel(
    const float* __restrict__ hlast,   // [B, H] normalized
    const float* __restrict__ Wlast,   // [C, H]
    const float* __restrict__ blast,   // [C]
    float*       __restrict__ out)     // [B, C]
{
    int b   = blockIdx.x;
    int tid = threadIdx.x;

    float acc[CC];
#pragma unroll
    for (int c = 0; c < CC; c++) acc[c] = 0.f;

    for (int h = tid; h < HH; h += 256) {
        float v = hlast[(size_t)b * HH + h];
#pragma unroll
        for (int c = 0; c < CC; c++)
            acc[c] += v * Wlast[c * HH + h];
    }

    __shared__ float sred[CC * 256];
#pragma unroll
    for (int c = 0; c < CC; c++) sred[c * 256 + tid] = acc[c];
    __syncthreads();

    for (int st = 128; st > 0; st >>= 1) {
        if (tid < st) {
#pragma unroll
            for (int c = 0; c < CC; c++)
                sred[c * 256 + tid] += sred[c * 256 + tid + st];
        }
        __syncthreads();
    }
    if (tid < CC)
        out[b * CC + tid] = sred[tid * 256] + blast[tid];
}

// ---------------------------------------------------------------------------
extern "C" void kernel_launch(void* const* d_in, const int* in_sizes, int n_in,
                              void* d_out, int out_size)
{
    const float* x      = (const float*)d_in[0];  // [8192, 144]
    const float* W0     = (const float*)d_in[1];  // [H, 144]
    const float* Ws     = (const float*)d_in[2];  // [L-1, H, H]
    const float* bs     = (const float*)d_in[3];
    const float* us     = (const float*)d_in[4];
    const float* gammas = (const float*)d_in[5];
    const float* betas  = (const float*)d_in[6];
    const float* Wlast  = (const float*)d_in[7];
    const float* blast  = (const float*)d_in[8];
    float* out = (float*)d_out;

    float *z, *h, *xr, *w0r, *wr;
    cudaGetSymbolAddress((void**)&z,   g_z);
    cudaGetSymbolAddress((void**)&h,   g_h);
    cudaGetSymbolAddress((void**)&xr,  g_x144);
    cudaGetSymbolAddress((void**)&w0r, g_W0r);
    cudaGetSymbolAddress((void**)&wr,  g_Wr);

    cudaFuncSetAttribute(gemm_tf32_pipe,
                         cudaFuncAttributeMaxDynamicSharedMemorySize,
                         GEMM_SMEM_BYTES);

    // pre-round all GEMM operands to tf32 (keeps numerics == wmma rna path)
    {
        int n4;
        n4 = NTB * KIN / 4;
        round_tf32_kernel<<<(n4 + 255) / 256, 256>>>(x, xr, n4);
        n4 = HH * KIN / 4;
        round_tf32_kernel<<<(n4 + 255) / 256, 256>>>(W0, w0r, n4);
        n4 = (LL - 1) * HH * HH / 4;
        round_tf32_kernel<<<(n4 + 255) / 256, 256>>>(Ws, wr, n4);
    }

    dim3 gemm_grid(HH / BN, NTB / BM);   // (16, 64)
    const int norm_blocks = (NTB * HH / 4 + 255) / 256;

    for (int l = 0; l < LL; l++) {
        const float* A = (l == 0) ? xr : h;
        const float* W = (l == 0) ? w0r : (wr + (size_t)(l - 1) * HH * HH);
        int K = (l == 0) ? KIN : HH;

        gemm_tf32_pipe<<<gemm_grid, 256, GEMM_SMEM_BYTES>>>(A, W, z, K);
        scan_kernel<<<BH / 256, 256>>>(z, h, us + (size_t)l * HH, bs + (size_t)l * HH);
        bn_params_kernel<<<HH / 256, 256>>>(gammas + (size_t)l * HH, betas + (size_t)l * HH);
        // layers 0..2: normalize + tf32-round (feeds next GEMM);
        // layer 3: normalize only (feeds fp32 final projection)
        normalize_kernel<<<norm_blocks, 256>>>(h, (l < LL - 1) ? 1 : 0);
    }

    final_kernel<<<BB, 256>>>(h + (size_t)(TT - 1) * BH, Wlast, blast, out);
}